// round 4
// baseline (speedup 1.0000x reference)
#include <cuda_runtime.h>
#include <cuda_fp16.h>

#define T_STEPS 256
#define NN      64
#define HH      512
#define DT_C    0.01f
#define NBLK    256
#define NTHR    256
#define RES_X   24                                  // Wx j-iters (of 32) resident in smem
#define DYN_SMEM (8 * RES_X * 2 * 16 * 16)          // 8 warps*24 it*2 hw*16 lanes*16B = 98304 B

// 64 MiB of fp16 transposed weights: layout [n][j][i]
__device__ __half g_Wh[(size_t)NN * HH * HH];
__device__ __half g_Wx[(size_t)NN * HH * HH];
__device__ unsigned g_state_cnt;        // +1 per block per step (monotonic)
__device__ unsigned g_hy_cnt[NN];       // +1 per sibling per step
__device__ unsigned g_ins_cnt[NN];      // +1 per sibling per step

// ---------------------------------------------------------------------------
__device__ __forceinline__ void arrive_rel(unsigned* ctr)
{
    asm volatile("red.release.gpu.add.u32 [%0], 1;" :: "l"(ctr) : "memory");
}
__device__ __forceinline__ unsigned ld_acq(unsigned* ctr)
{
    unsigned v;
    asm volatile("ld.acquire.gpu.u32 %0, [%1];" : "=r"(v) : "l"(ctr) : "memory");
    return v;
}
// all threads poll; each thread's own acquire orders its subsequent loads
__device__ __forceinline__ void wait_ge(unsigned* ctr, unsigned target)
{
    if (ld_acq(ctr) >= target) return;
    do { __nanosleep(30); } while (ld_acq(ctr) < target);
}

// ---------------------------------------------------------------------------
// packed fp32x2 helpers (sm_100a+)
__device__ __forceinline__ unsigned long long pack2(float x, float y)
{
    unsigned long long r;
    asm("mov.b64 %0, {%1, %2};" : "=l"(r) : "f"(x), "f"(y));
    return r;
}
__device__ __forceinline__ void ffma2(unsigned long long& acc, unsigned long long a,
                                      unsigned long long b)
{
    asm("fma.rn.f32x2 %0, %1, %2, %0;" : "+l"(acc) : "l"(a), "l"(b));
}
// acc[0..3] (f32x2 each) += w(8 fp16) * vv(broadcast f32x2)
__device__ __forceinline__ void fma8p(unsigned long long* acc, uint4 w, unsigned long long vv)
{
    float2 f0 = __half22float2(*reinterpret_cast<__half2*>(&w.x));
    float2 f1 = __half22float2(*reinterpret_cast<__half2*>(&w.y));
    float2 f2 = __half22float2(*reinterpret_cast<__half2*>(&w.z));
    float2 f3 = __half22float2(*reinterpret_cast<__half2*>(&w.w));
    ffma2(acc[0], pack2(f0.x, f0.y), vv);
    ffma2(acc[1], pack2(f1.x, f1.y), vv);
    ffma2(acc[2], pack2(f2.x, f2.y), vv);
    ffma2(acc[3], pack2(f3.x, f3.y), vv);
}

// ---------------------------------------------------------------------------
// fp32 [n][i][j]  ->  fp16 [n][j][i]   (transpose + convert, tiled)
// ---------------------------------------------------------------------------
__global__ void convert_transpose_kernel(const float* __restrict__ src, int which)
{
    __shared__ float tile[32][33];
    __half* dst = which ? g_Wx : g_Wh;
    const int nmat = blockIdx.z;
    const float* s = src + (size_t)nmat * HH * HH;
    __half*      d = dst + (size_t)nmat * HH * HH;
    const int x0 = blockIdx.x * 32;
    const int y0 = blockIdx.y * 32;
    #pragma unroll
    for (int k = threadIdx.y; k < 32; k += 8)
        tile[k][threadIdx.x] = s[(size_t)(y0 + k) * HH + x0 + threadIdx.x];
    __syncthreads();
    #pragma unroll
    for (int k = threadIdx.y; k < 32; k += 8)
        d[(size_t)(x0 + k) * HH + y0 + threadIdx.x] = __float2half_rn(tile[threadIdx.x][k]);
}

// ---------------------------------------------------------------------------
__global__ void init_out_kernel(const float* __restrict__ x,
                                const float* __restrict__ init_states,
                                float* __restrict__ states,
                                float* __restrict__ ins)
{
    const int i = blockIdx.x * blockDim.x + threadIdx.x;
    if (i < NN * 2 * HH) states[i] = init_states[i];
    if (i < NN * HH)     ins[i]    = x[i];
    if (i < NN)          { g_hy_cnt[i] = 0; g_ins_cnt[i] = 0; }
    if (i == 0)          g_state_cnt = 0;
}

// ---------------------------------------------------------------------------
// persistent RNN: 256 blocks = 4 per neuron (each 128 outputs), 2 blocks/SM.
// Wx mostly smem-resident (critical path after ins); Wh streamed from L2
// (hidden inside the sync window). Monotonic acquire/release counters.
// ---------------------------------------------------------------------------
__global__ void __launch_bounds__(NTHR, 2) rnn_kernel(
    const float* __restrict__ x,      // [T][N][H]
    const float* __restrict__ C,      // [N][N]
    const float* __restrict__ b,      // [N][H]
    float* __restrict__ states,       // [T+1][N][2][H]
    float* __restrict__ ins)          // [T+1][N][H]
{
    extern __shared__ __align__(16) unsigned char dynsmem[];
    uint4* sres = reinterpret_cast<uint4*>(dynsmem);

    __shared__ __align__(16) float sh_hy[HH];
    __shared__ __align__(16) float sh_ins[HH];
    __shared__ float sh_C[NN];
    __shared__ float sh_cm[2 * 128];
    __shared__ float sh_part[8 * 128];

    const int bid   = blockIdx.x;
    const int n     = bid >> 2;
    const int ibase = (bid & 3) * 128;
    const int tid   = threadIdx.x;
    const int warp  = tid >> 5;
    const int lane  = tid & 31;
    const int hw    = lane >> 4;          // half-warp: contiguous 32-j block
    const int li    = lane & 15;          // i-chunk (8 halves via uint4)
    const int jb    = warp * 64 + hw * 32; // this half-warp's j-base

    if (tid < NN) sh_C[tid] = C[n * NN + tid];
    const float bias = (tid < 128) ? b[n * HH + ibase + tid] : 0.0f;

    const __half* pWh = g_Wh + (size_t)n * HH * HH + (size_t)jb * HH + ibase + li * 8;
    const __half* pWx = g_Wx + (size_t)n * HH * HH + (size_t)jb * HH + ibase + li * 8;
    const int sbase = ((warp * RES_X) * 2 + hw) * 16 + li;   // + it*32 per iter

    // ---- stage resident Wx into shared (once) ----
    for (int it = 0; it < RES_X; ++it)
        sres[sbase + it * 32] = *reinterpret_cast<const uint4*>(pWx + (size_t)it * HH);

    // hz for own 128 outputs lives in a register across all steps
    float hz_r = (tid < 128) ? states[(n * 2 + 1) * HH + ibase + tid] : 0.0f;

    __syncthreads();

    for (int t = 0; t < T_STEPS; ++t) {
        const float* st  = states + (size_t)t * NN * 2 * HH;
        float*       stn = states + (size_t)(t + 1) * NN * 2 * HH;

        // ---- wait siblings' hy(t) chunks (cheap), load hy + x ---------------
        if (t > 0) wait_ge(&g_hy_cnt[n], 4u * (unsigned)t);
        reinterpret_cast<float2*>(sh_hy)[tid] =
            reinterpret_cast<const float2*>(st + n * 2 * HH)[tid];
        const float xv = (tid < 128) ? x[((size_t)t * NN + n) * HH + ibase + tid] : 0.0f;
        __syncthreads();                                            // bar1

        unsigned long long acc[4];
        #pragma unroll
        for (int k = 0; k < 4; ++k) acc[k] = pack2(0.0f, 0.0f);

        // ---- Wh.hy: all 32 iters streamed from L2 (hides global wait) ------
        #pragma unroll 2
        for (int it4 = 0; it4 < 8; ++it4) {
            const float4 hv = *reinterpret_cast<const float4*>(&sh_hy[jb + it4 * 4]);
            uint4 w0 = *reinterpret_cast<const uint4*>(pWh + (size_t)(it4 * 4 + 0) * HH);
            uint4 w1 = *reinterpret_cast<const uint4*>(pWh + (size_t)(it4 * 4 + 1) * HH);
            uint4 w2 = *reinterpret_cast<const uint4*>(pWh + (size_t)(it4 * 4 + 2) * HH);
            uint4 w3 = *reinterpret_cast<const uint4*>(pWh + (size_t)(it4 * 4 + 3) * HH);
            fma8p(acc, w0, pack2(hv.x, hv.x));
            fma8p(acc, w1, pack2(hv.y, hv.y));
            fma8p(acc, w2, pack2(hv.z, hv.z));
            fma8p(acc, w3, pack2(hv.w, hv.w));
        }

        // ---- global wait: all 256 blocks finished step t-1 ------------------
        if (t > 0) wait_ge(&g_state_cnt, 256u * (unsigned)t);

        // ---- distributed C-mix: ins chunk for own 128 j's ------------------
        {
            const int jloc = tid & 127;
            float cm = 0.0f;
            if (t > 0) {
                const int mb = (tid < 128) ? 0 : 32;
                const float* sp = st + (size_t)(2 * mb) * HH + ibase + jloc;
                #pragma unroll 16
                for (int m = 0; m < 32; ++m)
                    cm += sh_C[mb + m] * sp[(size_t)m * 2 * HH];
            }
            sh_cm[tid] = cm;
        }
        __syncthreads();                                            // bar2
        if (tid < 128) {
            const float v = (t > 0) ? (sh_cm[tid] + sh_cm[tid + 128]) * xv : 0.0f;
            ins[((size_t)(t + 1) * NN + n) * HH + ibase + tid] = v;
        }
        __syncthreads();                                            // bar3
        if (tid == 0) arrive_rel(&g_ins_cnt[n]);

        // ---- gather full ins(t+1) ------------------------------------------
        wait_ge(&g_ins_cnt[n], 4u * (unsigned)(t + 1));
        reinterpret_cast<float2*>(sh_ins)[tid] =
            reinterpret_cast<const float2*>(ins + ((size_t)(t + 1) * NN + n) * HH)[tid];
        __syncthreads();                                            // bar4

        // ---- Wx.ins: global tail first (burst), then resident smem iters ---
        #pragma unroll 2
        for (int it4 = RES_X / 4; it4 < 8; ++it4) {
            const float4 iv = *reinterpret_cast<const float4*>(&sh_ins[jb + it4 * 4]);
            uint4 w0 = *reinterpret_cast<const uint4*>(pWx + (size_t)(it4 * 4 + 0) * HH);
            uint4 w1 = *reinterpret_cast<const uint4*>(pWx + (size_t)(it4 * 4 + 1) * HH);
            uint4 w2 = *reinterpret_cast<const uint4*>(pWx + (size_t)(it4 * 4 + 2) * HH);
            uint4 w3 = *reinterpret_cast<const uint4*>(pWx + (size_t)(it4 * 4 + 3) * HH);
            fma8p(acc, w0, pack2(iv.x, iv.x));
            fma8p(acc, w1, pack2(iv.y, iv.y));
            fma8p(acc, w2, pack2(iv.z, iv.z));
            fma8p(acc, w3, pack2(iv.w, iv.w));
        }
        #pragma unroll 4
        for (int it4 = 0; it4 < RES_X / 4; ++it4) {
            const float4 iv = *reinterpret_cast<const float4*>(&sh_ins[jb + it4 * 4]);
            fma8p(acc, sres[sbase + (it4 * 4 + 0) * 32], pack2(iv.x, iv.x));
            fma8p(acc, sres[sbase + (it4 * 4 + 1) * 32], pack2(iv.y, iv.y));
            fma8p(acc, sres[sbase + (it4 * 4 + 2) * 32], pack2(iv.z, iv.z));
            fma8p(acc, sres[sbase + (it4 * 4 + 3) * 32], pack2(iv.w, iv.w));
        }

        // ---- reduce: half-warp pair via shfl, then 8 warps via shared -------
        float af[8];
        #pragma unroll
        for (int k = 0; k < 4; ++k)
            asm("mov.b64 {%0, %1}, %2;" : "=f"(af[2 * k]), "=f"(af[2 * k + 1]) : "l"(acc[k]));
        #pragma unroll
        for (int k = 0; k < 8; ++k)
            af[k] += __shfl_down_sync(0xffffffffu, af[k], 16);
        if (hw == 0) {
            #pragma unroll
            for (int k = 0; k < 8; ++k)
                sh_part[warp * 128 + li * 8 + k] = af[k];
        }
        __syncthreads();                                            // bar5

        // ---- state update (hz carried in registers) ------------------------
        if (tid < 128) {
            float s = bias;
            #pragma unroll
            for (int w2 = 0; w2 < 8; ++w2) s += sh_part[w2 * 128 + tid];
            const float hy   = sh_hy[ibase + tid];
            const float hz_n = hz_r + DT_C * (tanhf(s) - hy - hz_r);   // GAMMA=EPS=1
            const float hy_n = hy + DT_C * hz_n;
            hz_r = hz_n;
            stn[(n * 2 + 0) * HH + ibase + tid] = hy_n;
            stn[(n * 2 + 1) * HH + ibase + tid] = hz_n;
        }
        __syncthreads();                                            // bar6
        if (tid == 0) {
            arrive_rel(&g_hy_cnt[n]);      // siblings may start next Wh.hy
            arrive_rel(&g_state_cnt);      // everyone may start next C-mix
        }
    }
}

// ---------------------------------------------------------------------------
extern "C" void kernel_launch(void* const* d_in, const int* in_sizes, int n_in,
                              void* d_out, int out_size)
{
    const float* x   = (const float*)d_in[0];   // (256, 64, 512)
    const float* C   = (const float*)d_in[1];   // (64, 64)
    const float* Wh  = (const float*)d_in[2];   // (64, 512, 512)
    const float* Wx  = (const float*)d_in[3];   // (64, 512, 512)
    const float* b   = (const float*)d_in[4];   // (64, 512)
    const float* s0  = (const float*)d_in[5];   // (64, 2, 512)

    float* out    = (float*)d_out;
    float* states = out;                                          // (257,64,2,512)
    float* ins    = out + (size_t)(T_STEPS + 1) * NN * 2 * HH;    // (257,64,512)

    cudaFuncSetAttribute(rnn_kernel, cudaFuncAttributeMaxDynamicSharedMemorySize, DYN_SMEM);

    dim3 tb(32, 8, 1), tg(16, 16, NN);
    convert_transpose_kernel<<<tg, tb>>>(Wh, 0);
    convert_transpose_kernel<<<tg, tb>>>(Wx, 1);
    init_out_kernel<<<(NN * 2 * HH + 255) / 256, 256>>>(x, s0, states, ins);
    rnn_kernel<<<NBLK, NTHR, DYN_SMEM>>>(x, C, b, states, ins);
}